// round 2
// baseline (speedup 1.0000x reference)
#include <cuda_runtime.h>
#include <math.h>

#define BATCH 2
#define SEQ   2048
#define EMB   1024
#define NH    16
#define HD    64
#define ROWS  (BATCH*SEQ)      /* 4096 */
#define E3    (3*EMB)          /* 3072 */

// Scratch (allocation-free rule: __device__ globals)
__device__ float g_qkv[(size_t)ROWS * E3];    // [4096, 3072]
__device__ float g_attn[(size_t)ROWS * EMB];  // [4096, 1024]

// ---------------------------------------------------------------------------
// SGEMM + bias: C[M,N] = A[M,K] @ B[K,N] + bias[N]
// BM=BN=128, BK=16, 256 threads, 8x8 register tile per thread.
// ---------------------------------------------------------------------------
__global__ __launch_bounds__(256) void sgemm_bias_kernel(
    const float* __restrict__ A, const float* __restrict__ B,
    const float* __restrict__ bias, float* __restrict__ C,
    int M, int N, int K)
{
    __shared__ float As[128][17];   // padded: conflict-free column reads
    __shared__ float Bs[16][128];

    const int tid = threadIdx.x;
    const int ty = tid >> 4, tx = tid & 15;
    const int bm = blockIdx.y * 128, bn = blockIdx.x * 128;

    float acc[8][8];
    #pragma unroll
    for (int i = 0; i < 8; i++)
        #pragma unroll
        for (int j = 0; j < 8; j++) acc[i][j] = 0.f;

    for (int kt = 0; kt < K; kt += 16) {
        #pragma unroll
        for (int it = 0; it < 2; it++) {
            int f = tid + it * 256;
            // A tile: 128 rows x 16 cols = 512 float4
            int r  = f >> 2, c4 = f & 3;
            float4 a = *(const float4*)(A + (size_t)(bm + r) * K + kt + c4 * 4);
            As[r][c4*4+0] = a.x; As[r][c4*4+1] = a.y;
            As[r][c4*4+2] = a.z; As[r][c4*4+3] = a.w;
            // B tile: 16 rows x 128 cols = 512 float4
            int r2 = f >> 5, c2 = f & 31;
            float4 b = *(const float4*)(B + (size_t)(kt + r2) * N + bn + c2 * 4);
            *(float4*)&Bs[r2][c2*4] = b;
        }
        __syncthreads();

        #pragma unroll
        for (int kk = 0; kk < 16; kk++) {
            float ar[8], br[8];
            #pragma unroll
            for (int i = 0; i < 8; i++) ar[i] = As[ty*8 + i][kk];
            float4 b0 = *(float4*)&Bs[kk][tx*8];
            float4 b1 = *(float4*)&Bs[kk][tx*8 + 4];
            br[0]=b0.x; br[1]=b0.y; br[2]=b0.z; br[3]=b0.w;
            br[4]=b1.x; br[5]=b1.y; br[6]=b1.z; br[7]=b1.w;
            #pragma unroll
            for (int i = 0; i < 8; i++)
                #pragma unroll
                for (int j = 0; j < 8; j++)
                    acc[i][j] = fmaf(ar[i], br[j], acc[i][j]);
        }
        __syncthreads();
    }

    float bb[8];
    #pragma unroll
    for (int j = 0; j < 8; j++) bb[j] = bias[bn + tx*8 + j];

    #pragma unroll
    for (int i = 0; i < 8; i++) {
        float* cp = C + (size_t)(bm + ty*8 + i) * N + bn + tx*8;
        float4 o0 = make_float4(acc[i][0]+bb[0], acc[i][1]+bb[1], acc[i][2]+bb[2], acc[i][3]+bb[3]);
        float4 o1 = make_float4(acc[i][4]+bb[4], acc[i][5]+bb[5], acc[i][6]+bb[6], acc[i][7]+bb[7]);
        *(float4*)cp       = o0;
        *(float4*)(cp + 4) = o1;
    }
}

// ---------------------------------------------------------------------------
// Fused flash-attention: per (batch, head, 128-query block).
// BM=128 queries, BN=64 keys/iter, D=64. 256 threads as 16x16.
// S tile 8x4 per thread; O tile 8x4 per thread. Online softmax.
// smem: Qt[64][128] | Kt[64][64] | Vs[64][64] | Ps[128][65]  = 98816 B
// ---------------------------------------------------------------------------
#define ATTN_SMEM_FLOATS (64*128 + 64*64 + 64*64 + 128*65)

__global__ __launch_bounds__(256) void attn_kernel(
    const float* __restrict__ qkv, float* __restrict__ outp)
{
    extern __shared__ float sm[];
    float* Qt = sm;                      // [64][128]  (d-major, q scaled)
    float* Kt = Qt + 64*128;             // [64][64]   (d-major)
    float* Vs = Kt + 64*64;              // [64][64]   (r-major)
    float* Ps = Vs + 64*64;              // [128][65]  (padded)

    const int tid = threadIdx.x;
    const int ty = tid >> 4, tx = tid & 15;
    const int b = blockIdx.z, h = blockIdx.y, q0 = blockIdx.x * 128;
    const float scale = 0.125f;          // 1/sqrt(64)

    // Load Q block transposed & pre-scaled: 128 rows x 64 cols (16 float4/row)
    {
        const size_t base_q = (size_t)(b*SEQ + q0) * E3 + h*HD;
        for (int f = tid; f < 2048; f += 256) {
            int r = f >> 4, c4 = f & 15;
            float4 q = *(const float4*)(qkv + base_q + (size_t)r * E3 + c4*4);
            Qt[(c4*4+0)*128 + r] = q.x * scale;
            Qt[(c4*4+1)*128 + r] = q.y * scale;
            Qt[(c4*4+2)*128 + r] = q.z * scale;
            Qt[(c4*4+3)*128 + r] = q.w * scale;
        }
    }

    float m_i[8], l_i[8], O[8][4];
    #pragma unroll
    for (int i = 0; i < 8; i++) {
        m_i[i] = -INFINITY; l_i[i] = 0.f;
        #pragma unroll
        for (int j = 0; j < 4; j++) O[i][j] = 0.f;
    }
    __syncthreads();

    for (int kb = 0; kb < SEQ; kb += 64) {
        // Load K (transposed) and V (row-major): 64 rows x 16 float4 each
        const size_t base_k = (size_t)(b*SEQ + kb) * E3 + EMB   + h*HD;
        const size_t base_v = (size_t)(b*SEQ + kb) * E3 + 2*EMB + h*HD;
        for (int f = tid; f < 1024; f += 256) {
            int r = f >> 4, c4 = f & 15;
            float4 kq = *(const float4*)(qkv + base_k + (size_t)r * E3 + c4*4);
            Kt[(c4*4+0)*64 + r] = kq.x;
            Kt[(c4*4+1)*64 + r] = kq.y;
            Kt[(c4*4+2)*64 + r] = kq.z;
            Kt[(c4*4+3)*64 + r] = kq.w;
            float4 vq = *(const float4*)(qkv + base_v + (size_t)r * E3 + c4*4);
            *(float4*)&Vs[r*64 + c4*4] = vq;
        }
        __syncthreads();

        // S = (Q*scale) @ K^T : 8x4 per thread
        float s[8][4];
        #pragma unroll
        for (int i = 0; i < 8; i++)
            #pragma unroll
            for (int j = 0; j < 4; j++) s[i][j] = 0.f;

        #pragma unroll 8
        for (int d = 0; d < 64; d++) {
            float qv[8];
            #pragma unroll
            for (int i = 0; i < 8; i++) qv[i] = Qt[d*128 + ty*8 + i];
            float4 kv = *(float4*)&Kt[d*64 + tx*4];
            #pragma unroll
            for (int i = 0; i < 8; i++) {
                s[i][0] = fmaf(qv[i], kv.x, s[i][0]);
                s[i][1] = fmaf(qv[i], kv.y, s[i][1]);
                s[i][2] = fmaf(qv[i], kv.z, s[i][2]);
                s[i][3] = fmaf(qv[i], kv.w, s[i][3]);
            }
        }

        // Online softmax update (row reductions over 16 tx lanes via shfl)
        #pragma unroll
        for (int i = 0; i < 8; i++) {
            float rm = fmaxf(fmaxf(s[i][0], s[i][1]), fmaxf(s[i][2], s[i][3]));
            #pragma unroll
            for (int off = 8; off >= 1; off >>= 1)
                rm = fmaxf(rm, __shfl_xor_sync(0xffffffffu, rm, off));
            float mnew = fmaxf(m_i[i], rm);
            float corr = __expf(m_i[i] - mnew);
            m_i[i] = mnew;
            float rs = 0.f;
            #pragma unroll
            for (int j = 0; j < 4; j++) {
                float p = __expf(s[i][j] - mnew);
                s[i][j] = p; rs += p;
            }
            #pragma unroll
            for (int off = 8; off >= 1; off >>= 1)
                rs += __shfl_xor_sync(0xffffffffu, rs, off);
            l_i[i] = l_i[i] * corr + rs;
            #pragma unroll
            for (int j = 0; j < 4; j++) {
                O[i][j] *= corr;
                Ps[(ty*8 + i)*65 + tx*4 + j] = s[i][j];
            }
        }
        __syncthreads();

        // O += P @ V
        #pragma unroll 8
        for (int k = 0; k < 64; k++) {
            float pv[8];
            #pragma unroll
            for (int i = 0; i < 8; i++) pv[i] = Ps[(ty*8 + i)*65 + k];
            float4 vv = *(float4*)&Vs[k*64 + tx*4];
            #pragma unroll
            for (int i = 0; i < 8; i++) {
                O[i][0] = fmaf(pv[i], vv.x, O[i][0]);
                O[i][1] = fmaf(pv[i], vv.y, O[i][1]);
                O[i][2] = fmaf(pv[i], vv.z, O[i][2]);
                O[i][3] = fmaf(pv[i], vv.w, O[i][3]);
            }
        }
        __syncthreads();
    }

    // Normalize and store: out[b, q0+row, h*64 + tx*4 .. +3]
    #pragma unroll
    for (int i = 0; i < 8; i++) {
        float inv = 1.0f / l_i[i];
        float4 o = make_float4(O[i][0]*inv, O[i][1]*inv, O[i][2]*inv, O[i][3]*inv);
        *(float4*)(outp + (size_t)(b*SEQ + q0 + ty*8 + i) * EMB + h*HD + tx*4) = o;
    }
}

// ---------------------------------------------------------------------------
extern "C" void kernel_launch(void* const* d_in, const int* in_sizes, int n_in,
                              void* d_out, int out_size)
{
    const float* x     = (const float*)d_in[0];
    const float* w_in  = (const float*)d_in[1];
    const float* b_in  = (const float*)d_in[2];
    const float* w_out = (const float*)d_in[3];
    const float* b_out = (const float*)d_in[4];
    float* out = (float*)d_out;

    float *qkv = nullptr, *attn = nullptr;
    cudaGetSymbolAddress((void**)&qkv,  g_qkv);
    cudaGetSymbolAddress((void**)&attn, g_attn);

    // 1) QKV projection: [4096,1024] @ [1024,3072] + b_in
    sgemm_bias_kernel<<<dim3(E3/128, ROWS/128), 256>>>(x, w_in, b_in, qkv,
                                                       ROWS, E3, EMB);

    // 2) Fused attention: grid (q-blocks, heads, batch)
    static bool attr_set = false;
    if (!attr_set) {
        cudaFuncSetAttribute(attn_kernel,
                             cudaFuncAttributeMaxDynamicSharedMemorySize,
                             ATTN_SMEM_FLOATS * (int)sizeof(float));
        attr_set = true;
    }
    attn_kernel<<<dim3(SEQ/128, NH, BATCH), 256,
                  ATTN_SMEM_FLOATS * sizeof(float)>>>(qkv, attn);

    // 3) Output projection: [4096,1024] @ [1024,1024] + b_out
    sgemm_bias_kernel<<<dim3(EMB/128, ROWS/128), 256>>>(attn, w_out, b_out, out,
                                                        ROWS, EMB, EMB);
}

// round 4
// speedup vs baseline: 1.7342x; 1.7342x over previous
#include <cuda_runtime.h>
#include <math.h>
#include <stdint.h>

#define BATCH 2
#define SEQ   2048
#define EMB   1024
#define NH    16
#define HD    64
#define ROWS  (BATCH*SEQ)      /* 4096 */
#define E3    (3*EMB)          /* 3072 */

// Scratch (allocation-free rule: __device__ globals)
__device__ float g_qkv[(size_t)ROWS * E3];    // [4096, 3072]
__device__ float g_attn[(size_t)ROWS * EMB];  // [4096, 1024]

// ===========================================================================
// mma.sync m16n8k8 tf32 helpers (generic PTX — compiles for compute_103)
// Fragment layouts (PTX ISA):
//  A(16x8): a0=(g,t) a1=(g+8,t) a2=(g,t+4) a3=(g+8,t+4)   g=lane>>2, t=lane&3
//  B(8x8) : b0=(k=t, n=g)  b1=(k=t+4, n=g)
//  C(16x8): c0=(g,2t) c1=(g,2t+1) c2=(g+8,2t) c3=(g+8,2t+1)
// ===========================================================================
__device__ __forceinline__ uint32_t tf32_of(float x) {
    uint32_t r;
    asm("cvt.rna.tf32.f32 %0, %1;" : "=r"(r) : "f"(x));
    return r;
}
__device__ __forceinline__ void mma_tf32(float c[4], const uint32_t a[4],
                                         const uint32_t b[2]) {
    asm volatile(
        "mma.sync.aligned.m16n8k8.row.col.f32.tf32.tf32.f32 "
        "{%0,%1,%2,%3}, {%4,%5,%6,%7}, {%8,%9}, {%0,%1,%2,%3};"
        : "+f"(c[0]), "+f"(c[1]), "+f"(c[2]), "+f"(c[3])
        : "r"(a[0]), "r"(a[1]), "r"(a[2]), "r"(a[3]), "r"(b[0]), "r"(b[1]));
}

// ===========================================================================
// GEMM + bias: C[M,N] = A[M,K] @ B[K,N] + bias[N]
// 128x128 CTA tile, BK=16, 256 threads (8 warps: 2 m x 4 n, 64x32 per warp).
// SMEM holds tiles in exact fragment layout (A: float4/lane, B: float2/lane).
// ===========================================================================
__global__ __launch_bounds__(256) void mma_gemm_bias(
    const float* __restrict__ A, const float* __restrict__ B,
    const float* __restrict__ bias, float* __restrict__ C,
    int M, int N, int K)
{
    __shared__ uint32_t As[2048];   // 8 mtile x 2 kf x 32 lane x 4
    __shared__ uint32_t Bs[2048];   // 16 ntile x 2 kf x 32 lane x 2

    const int tid  = threadIdx.x;
    const int lane = tid & 31, wid = tid >> 5;
    const int wm = wid >> 2, wn = wid & 3;
    const int g = lane >> 2, t4 = lane & 3;
    const int bm = blockIdx.y * 128, bn = blockIdx.x * 128;

    float acc[4][4][4];
    #pragma unroll
    for (int mt = 0; mt < 4; mt++)
        #pragma unroll
        for (int nt = 0; nt < 4; nt++)
            #pragma unroll
            for (int j = 0; j < 4; j++) acc[mt][nt][j] = 0.f;

    // writer roles
    const int arow = tid >> 1, akb = (tid & 1) * 8;      // A: row, k-half
    const int brow = tid >> 4, bnb = (tid & 15) * 8;     // B: k-row, n-chunk
    const float* Abase = A + (size_t)(bm + arow) * K + akb;
    const float* Bbase = B + (size_t)brow * N + bn + bnb;

    const int NT = K / 16;
    float4 aR0, aR1, bR0, bR1;
    aR0 = *(const float4*)(Abase);
    aR1 = *(const float4*)(Abase + 4);
    bR0 = *(const float4*)(Bbase);
    bR1 = *(const float4*)(Bbase + 4);

    for (int kt = 0; kt < NT; kt++) {
        // ---- store staged tile into fragment-layout smem ----
        {
            float av[8] = {aR0.x, aR0.y, aR0.z, aR0.w, aR1.x, aR1.y, aR1.z, aR1.w};
            const int mt = arow >> 4, r = arow & 15;
            #pragma unroll
            for (int j = 0; j < 8; j++) {
                const int kk = akb + j, kf = kk >> 3, cc = kk & 7;
                const int idx = (((mt * 2 + kf) * 32 + (r & 7) * 4 + (cc & 3)) << 2)
                                + ((r >> 3) | ((cc >> 2) << 1));
                As[idx] = tf32_of(av[j]);
            }
            float bv[8] = {bR0.x, bR0.y, bR0.z, bR0.w, bR1.x, bR1.y, bR1.z, bR1.w};
            const int kf = brow >> 3, k8 = brow & 7;
            #pragma unroll
            for (int j = 0; j < 8; j++) {
                const int n = bnb + j;
                const int idx = ((((n >> 3) * 2 + kf) * 32 + (n & 7) * 4 + (k8 & 3)) << 1)
                                + (k8 >> 2);
                Bs[idx] = tf32_of(bv[j]);
            }
        }
        __syncthreads();

        // ---- prefetch next tile into regs (hides gmem latency under MMA) ----
        if (kt + 1 < NT) {
            const float* Ap = Abase + (kt + 1) * 16;
            aR0 = *(const float4*)(Ap);
            aR1 = *(const float4*)(Ap + 4);
            const float* Bp = Bbase + (size_t)(kt + 1) * 16 * N;
            bR0 = *(const float4*)(Bp);
            bR1 = *(const float4*)(Bp + 4);
        }

        // ---- compute: 2 kf x (4 mt x 4 nt) mma ----
        #pragma unroll
        for (int kf = 0; kf < 2; kf++) {
            uint32_t af[4][4], bf[4][2];
            #pragma unroll
            for (int mt = 0; mt < 4; mt++) {
                uint4 v = *(const uint4*)&As[(((wm * 4 + mt) * 2 + kf) * 32 + lane) * 4];
                af[mt][0] = v.x; af[mt][1] = v.y; af[mt][2] = v.z; af[mt][3] = v.w;
            }
            #pragma unroll
            for (int nt = 0; nt < 4; nt++) {
                uint2 v = *(const uint2*)&Bs[(((wn * 4 + nt) * 2 + kf) * 32 + lane) * 2];
                bf[nt][0] = v.x; bf[nt][1] = v.y;
            }
            #pragma unroll
            for (int mt = 0; mt < 4; mt++)
                #pragma unroll
                for (int nt = 0; nt < 4; nt++)
                    mma_tf32(acc[mt][nt], af[mt], bf[nt]);
        }
        __syncthreads();
    }

    // ---- epilogue: C-fragment scatter + bias ----
    #pragma unroll
    for (int mt = 0; mt < 4; mt++) {
        const int row = bm + wm * 64 + mt * 16 + g;
        #pragma unroll
        for (int nt = 0; nt < 4; nt++) {
            const int col = bn + wn * 32 + nt * 8 + t4 * 2;
            const float b0 = bias[col], b1 = bias[col + 1];
            *(float2*)(C + (size_t)row * N + col) =
                make_float2(acc[mt][nt][0] + b0, acc[mt][nt][1] + b1);
            *(float2*)(C + (size_t)(row + 8) * N + col) =
                make_float2(acc[mt][nt][2] + b0, acc[mt][nt][3] + b1);
        }
    }
}

// ===========================================================================
// Flash attention on mma.sync tf32.
// CTA = (128 q-rows, head h, batch b). 8 warps, warp = 16 q-rows (full rows
// => softmax reductions are quad-local). BN=64 keys/iter, D=64.
// Q held in registers as A-fragments for the whole kernel.
// K/V staged per iter into fragment-layout smem. P: C-frag -> A-frag via
// quad shuffles (no smem round trip).
// ===========================================================================
__global__ __launch_bounds__(256) void mma_attn(
    const float* __restrict__ qkv, float* __restrict__ outp)
{
    __shared__ uint32_t Ksm[4096];  // 8 s-tile x 8 kf(d) x 32 lane x 2
    __shared__ uint32_t Vsm[4096];  // 8 d-tile x 8 kf(s) x 32 lane x 2

    const int tid  = threadIdx.x;
    const int lane = tid & 31, wq = tid >> 5;
    const int g = lane >> 2, t4 = lane & 3;
    const int b = blockIdx.z, h = blockIdx.y, q0 = blockIdx.x * 128;

    // ---- Q fragments (pre-scaled, tf32) held in registers ----
    uint32_t qa[8][4];
    {
        const float scale = 0.125f;  // 1/sqrt(64)
        const size_t r0 = (size_t)(b * SEQ + q0 + wq * 16 + g) * E3 + h * HD;
        const size_t r1 = r0 + (size_t)8 * E3;
        #pragma unroll
        for (int kf = 0; kf < 8; kf++) {
            const int c = kf * 8 + t4;
            qa[kf][0] = tf32_of(qkv[r0 + c] * scale);
            qa[kf][1] = tf32_of(qkv[r1 + c] * scale);
            qa[kf][2] = tf32_of(qkv[r0 + c + 4] * scale);
            qa[kf][3] = tf32_of(qkv[r1 + c + 4] * scale);
        }
    }

    float O[8][4];
    #pragma unroll
    for (int nt = 0; nt < 8; nt++)
        #pragma unroll
        for (int j = 0; j < 4; j++) O[nt][j] = 0.f;
    float m0 = -INFINITY, m1 = -INFINITY, l0 = 0.f, l1 = 0.f;

    // K/V staging role: thread -> (s row, 16-wide d chunk)
    const int sR = tid >> 2, dB = (tid & 3) * 16;
    float4 kR[4], vR[4];
    {
        const size_t base = (size_t)(b * SEQ + sR) * E3 + h * HD + dB;
        #pragma unroll
        for (int i = 0; i < 4; i++) {
            kR[i] = *(const float4*)(qkv + base + EMB + i * 4);
            vR[i] = *(const float4*)(qkv + base + 2 * EMB + i * 4);
        }
    }

    for (int kb = 0; kb < SEQ; kb += 64) {
        // ---- store staged K/V into fragment-layout smem ----
        #pragma unroll
        for (int i = 0; i < 4; i++) {
            float kv[4] = {kR[i].x, kR[i].y, kR[i].z, kR[i].w};
            float vv[4] = {vR[i].x, vR[i].y, vR[i].z, vR[i].w};
            #pragma unroll
            for (int j = 0; j < 4; j++) {
                const int d = dB + i * 4 + j;
                // K tile: B-frag with n=s, k=d
                const int kidx = ((((sR >> 3) * 8 + (d >> 3)) * 32
                                   + (sR & 7) * 4 + (d & 3)) << 1) + ((d >> 2) & 1);
                Ksm[kidx] = tf32_of(kv[j]);
                // V tile: B-frag with n=d, k=s
                const int vidx = ((((d >> 3) * 8 + (sR >> 3)) * 32
                                   + (d & 7) * 4 + (sR & 3)) << 1) + ((sR >> 2) & 1);
                Vsm[vidx] = tf32_of(vv[j]);
            }
        }
        __syncthreads();

        // ---- prefetch next K/V block ----
        if (kb + 64 < SEQ) {
            const size_t base = (size_t)(b * SEQ + kb + 64 + sR) * E3 + h * HD + dB;
            #pragma unroll
            for (int i = 0; i < 4; i++) {
                kR[i] = *(const float4*)(qkv + base + EMB + i * 4);
                vR[i] = *(const float4*)(qkv + base + 2 * EMB + i * 4);
            }
        }

        // ---- S = Q @ K^T : 8 nt(s-tiles) x 8 kf(d-groups) ----
        float sc[8][4];
        #pragma unroll
        for (int nt = 0; nt < 8; nt++)
            #pragma unroll
            for (int j = 0; j < 4; j++) sc[nt][j] = 0.f;
        #pragma unroll
        for (int kf = 0; kf < 8; kf++) {
            #pragma unroll
            for (int nt = 0; nt < 8; nt++) {
                uint2 v = *(const uint2*)&Ksm[((nt * 8 + kf) * 32 + lane) * 2];
                uint32_t bb[2] = {v.x, v.y};
                mma_tf32(sc[nt], qa[kf], bb);
            }
        }

        // ---- online softmax (rows g and g+8; quad-local reductions) ----
        float mx0 = -INFINITY, mx1 = -INFINITY;
        #pragma unroll
        for (int nt = 0; nt < 8; nt++) {
            mx0 = fmaxf(mx0, fmaxf(sc[nt][0], sc[nt][1]));
            mx1 = fmaxf(mx1, fmaxf(sc[nt][2], sc[nt][3]));
        }
        mx0 = fmaxf(mx0, __shfl_xor_sync(0xffffffffu, mx0, 1));
        mx0 = fmaxf(mx0, __shfl_xor_sync(0xffffffffu, mx0, 2));
        mx1 = fmaxf(mx1, __shfl_xor_sync(0xffffffffu, mx1, 1));
        mx1 = fmaxf(mx1, __shfl_xor_sync(0xffffffffu, mx1, 2));
        const float mn0 = fmaxf(m0, mx0), mn1 = fmaxf(m1, mx1);
        const float corr0 = __expf(m0 - mn0), corr1 = __expf(m1 - mn1);
        m0 = mn0; m1 = mn1;
        float rs0 = 0.f, rs1 = 0.f;
        #pragma unroll
        for (int nt = 0; nt < 8; nt++) {
            sc[nt][0] = __expf(sc[nt][0] - mn0);
            sc[nt][1] = __expf(sc[nt][1] - mn0);
            sc[nt][2] = __expf(sc[nt][2] - mn1);
            sc[nt][3] = __expf(sc[nt][3] - mn1);
            rs0 += sc[nt][0] + sc[nt][1];
            rs1 += sc[nt][2] + sc[nt][3];
        }
        rs0 += __shfl_xor_sync(0xffffffffu, rs0, 1);
        rs0 += __shfl_xor_sync(0xffffffffu, rs0, 2);
        rs1 += __shfl_xor_sync(0xffffffffu, rs1, 1);
        rs1 += __shfl_xor_sync(0xffffffffu, rs1, 2);
        l0 = l0 * corr0 + rs0;
        l1 = l1 * corr1 + rs1;
        #pragma unroll
        for (int nt = 0; nt < 8; nt++) {
            O[nt][0] *= corr0; O[nt][1] *= corr0;
            O[nt][2] *= corr1; O[nt][3] *= corr1;
        }

        // ---- O += P @ V : convert P C-frag -> A-frag via quad shuffles ----
        const int qb = lane & ~3;
        const int src0 = qb + (t4 >> 1), src1 = src0 + 2;
        const bool odd = (t4 & 1);
        #pragma unroll
        for (int kf = 0; kf < 8; kf++) {
            float w00 = __shfl_sync(0xffffffffu, sc[kf][0], src0);
            float w01 = __shfl_sync(0xffffffffu, sc[kf][1], src0);
            float w10 = __shfl_sync(0xffffffffu, sc[kf][2], src0);
            float w11 = __shfl_sync(0xffffffffu, sc[kf][3], src0);
            float w20 = __shfl_sync(0xffffffffu, sc[kf][0], src1);
            float w21 = __shfl_sync(0xffffffffu, sc[kf][1], src1);
            float w30 = __shfl_sync(0xffffffffu, sc[kf][2], src1);
            float w31 = __shfl_sync(0xffffffffu, sc[kf][3], src1);
            uint32_t pa[4];
            pa[0] = tf32_of(odd ? w01 : w00);
            pa[1] = tf32_of(odd ? w11 : w10);
            pa[2] = tf32_of(odd ? w21 : w20);
            pa[3] = tf32_of(odd ? w31 : w30);
            #pragma unroll
            for (int nt = 0; nt < 8; nt++) {
                uint2 v = *(const uint2*)&Vsm[((nt * 8 + kf) * 32 + lane) * 2];
                uint32_t bb[2] = {v.x, v.y};
                mma_tf32(O[nt], pa, bb);
            }
        }
        __syncthreads();
    }

    // ---- normalize + store ----
    const float inv0 = 1.f / l0, inv1 = 1.f / l1;
    const size_t ro = (size_t)(b * SEQ + q0 + wq * 16 + g) * EMB + h * HD;
    #pragma unroll
    for (int nt = 0; nt < 8; nt++) {
        const int c = nt * 8 + t4 * 2;
        *(float2*)(outp + ro + c) = make_float2(O[nt][0] * inv0, O[nt][1] * inv0);
        *(float2*)(outp + ro + (size_t)8 * EMB + c) =
            make_float2(O[nt][2] * inv1, O[nt][3] * inv1);
    }
}

// ---------------------------------------------------------------------------
extern "C" void kernel_launch(void* const* d_in, const int* in_sizes, int n_in,
                              void* d_out, int out_size)
{
    const float* x     = (const float*)d_in[0];
    const float* w_in  = (const float*)d_in[1];
    const float* b_in  = (const float*)d_in[2];
    const float* w_out = (const float*)d_in[3];
    const float* b_out = (const float*)d_in[4];
    float* out = (float*)d_out;

    float *qkv = nullptr, *attn = nullptr;
    cudaGetSymbolAddress((void**)&qkv,  g_qkv);
    cudaGetSymbolAddress((void**)&attn, g_attn);

    // 1) QKV projection: [4096,1024] @ [1024,3072] + b_in
    mma_gemm_bias<<<dim3(E3 / 128, ROWS / 128), 256>>>(x, w_in, b_in, qkv,
                                                       ROWS, E3, EMB);

    // 2) Fused attention
    mma_attn<<<dim3(SEQ / 128, NH, BATCH), 256>>>(qkv, attn);

    // 3) Output projection: [4096,1024] @ [1024,1024] + b_out
    mma_gemm_bias<<<dim3(EMB / 128, ROWS / 128), 256>>>(attn, w_out, b_out, out,
                                                        ROWS, EMB, EMB);
}

// round 5
// speedup vs baseline: 2.9320x; 1.6907x over previous
#include <cuda_runtime.h>
#include <math.h>
#include <stdint.h>

#define BATCH 2
#define SEQ   2048
#define EMB   1024
#define NH    16
#define HD    64
#define ROWS  (BATCH*SEQ)      /* 4096 */
#define E3    (3*EMB)          /* 3072 */

// Scratch (allocation-free rule: __device__ globals)
__device__ float g_qkv[(size_t)ROWS * E3];    // [4096, 3072]
__device__ float g_attn[(size_t)ROWS * EMB];  // [4096, 1024]

// ===========================================================================
// mma.sync m16n8k8 tf32 helpers (generic PTX — compiles for compute_103)
//  A(16x8): a0=(g,t) a1=(g+8,t) a2=(g,t+4) a3=(g+8,t+4)   g=lane>>2, t=lane&3
//  B(8x8) : b0=(k=t, n=g)  b1=(k=t+4, n=g)
//  C(16x8): c0=(g,2t) c1=(g,2t+1) c2=(g+8,2t) c3=(g+8,2t+1)
// ===========================================================================
__device__ __forceinline__ uint32_t tf32_of(float x) {
    uint32_t r;
    asm("cvt.rna.tf32.f32 %0, %1;" : "=r"(r) : "f"(x));
    return r;
}
__device__ __forceinline__ void mma_tf32(float c[4], const uint32_t a[4],
                                         const uint32_t b[2]) {
    asm volatile(
        "mma.sync.aligned.m16n8k8.row.col.f32.tf32.tf32.f32 "
        "{%0,%1,%2,%3}, {%4,%5,%6,%7}, {%8,%9}, {%0,%1,%2,%3};"
        : "+f"(c[0]), "+f"(c[1]), "+f"(c[2]), "+f"(c[3])
        : "r"(a[0]), "r"(a[1]), "r"(a[2]), "r"(a[3]), "r"(b[0]), "r"(b[1]));
}
__device__ __forceinline__ void cp16(uint32_t dst, const void* src) {
    asm volatile("cp.async.cg.shared.global [%0], [%1], 16;"
                 :: "r"(dst), "l"(src));
}
__device__ __forceinline__ uint32_t smem_u32(const void* p) {
    uint32_t a;
    asm("{ .reg .u64 t; cvta.to.shared.u64 t, %1; cvt.u32.u64 %0, t; }"
        : "=r"(a) : "l"(p));
    return a;
}

// ===========================================================================
// GEMM + bias: C[M,N] = A[M,K] @ B[K,N] + bias[N]
// 128x128 CTA tile, BK=32, 3-stage cp.async pipeline, 256 threads
// (8 warps: 2m x 4n, warp tile 64x32). Raw fp32 -> tf32 truncation in MMA.
// SMEM/stage: A 128x32 (16KB, chunk swizzle c^=r&7) + B 32x128 (16KB,
// chunk swizzle c^=k&7) = 32KB; 3 stages = 96KB dynamic.
// ===========================================================================
#define GS 3
#define GEMM_SMEM_BYTES (GS * 32768)

__global__ __launch_bounds__(256, 2) void mma_gemm_bias(
    const float* __restrict__ A, const float* __restrict__ B,
    const float* __restrict__ bias, float* __restrict__ C,
    int M, int N, int K)
{
    extern __shared__ uint32_t sm[];
    const uint32_t sbase = smem_u32(sm);
    const int tid  = threadIdx.x;
    const int lane = tid & 31, wid = tid >> 5;
    const int wm = wid >> 2, wn = wid & 3;
    const int g = lane >> 2, t4 = lane & 3;
    const int bm = blockIdx.y * 128, bn = blockIdx.x * 128;

    // cp.async roles (4 chunks each for A and B per stage)
    const int ar0 = tid >> 3, ac = tid & 7;     // A: rows ar0+32i, chunk ac
    const int bk0 = tid >> 5, bc = tid & 31;    // B: k-rows bk0+8i, chunk bc

    float acc[4][4][4];
    #pragma unroll
    for (int mt = 0; mt < 4; mt++)
        #pragma unroll
        for (int nt = 0; nt < 4; nt++)
            #pragma unroll
            for (int j = 0; j < 4; j++) acc[mt][nt][j] = 0.f;

    const int NT = K / 32;

    // ---- stage issuer ----
    auto issue = [&](int slot, int kt) {
        const uint32_t aw = sbase + slot * 32768;
        #pragma unroll
        for (int i = 0; i < 4; i++) {
            const int r = ar0 + i * 32;
            cp16(aw + (uint32_t)(r * 32 + ((ac ^ (r & 7)) << 2)) * 4,
                 A + (size_t)(bm + r) * K + kt * 32 + ac * 4);
        }
        const uint32_t bw = aw + 16384;
        #pragma unroll
        for (int i = 0; i < 4; i++) {
            const int k = bk0 + i * 8;
            cp16(bw + (uint32_t)(k * 128 + ((bc ^ (k & 7)) << 2)) * 4,
                 B + (size_t)(kt * 32 + k) * N + bn + bc * 4);
        }
    };

    // prologue: fill GS-1 stages
    #pragma unroll
    for (int s = 0; s < GS - 1; s++) {
        issue(s, s);
        asm volatile("cp.async.commit_group;" ::: "memory");
    }

    for (int kt = 0; kt < NT; kt++) {
        asm volatile("cp.async.wait_group 1;" ::: "memory");
        __syncthreads();

        const int slot = kt % GS;
        if (kt + GS - 1 < NT) issue((kt + GS - 1) % GS, kt + GS - 1);
        asm volatile("cp.async.commit_group;" ::: "memory");

        const uint32_t* Aw = sm + slot * 8192;
        const uint32_t* Bw = Aw + 4096;

        #pragma unroll
        for (int kf = 0; kf < 4; kf++) {
            uint32_t af[4][4];
            const int x = (2 * kf) ^ g;
            #pragma unroll
            for (int mt = 0; mt < 4; mt++) {
                const uint32_t* p = Aw + (wm * 64 + mt * 16 + g) * 32 + t4;
                af[mt][0] = p[x << 2];
                af[mt][1] = p[256 + (x << 2)];
                af[mt][2] = p[(x ^ 1) << 2];
                af[mt][3] = p[256 + ((x ^ 1) << 2)];
            }
            uint32_t bf[4][2];
            const uint32_t* q = Bw + (kf * 8 + t4) * 128 + (g & 3);
            #pragma unroll
            for (int nt = 0; nt < 4; nt++) {
                const int ct = (wn * 8 + nt * 2 + (g >> 2)) ^ t4;
                bf[nt][0] = q[ct << 2];
                bf[nt][1] = q[512 + ((ct ^ 4) << 2)];
            }
            #pragma unroll
            for (int mt = 0; mt < 4; mt++)
                #pragma unroll
                for (int nt = 0; nt < 4; nt++)
                    mma_tf32(acc[mt][nt], af[mt], bf[nt]);
        }
    }

    // ---- epilogue: C-fragment scatter + bias ----
    #pragma unroll
    for (int mt = 0; mt < 4; mt++) {
        const int row = bm + wm * 64 + mt * 16 + g;
        #pragma unroll
        for (int nt = 0; nt < 4; nt++) {
            const int col = bn + wn * 32 + nt * 8 + t4 * 2;
            const float b0 = bias[col], b1 = bias[col + 1];
            *(float2*)(C + (size_t)row * N + col) =
                make_float2(acc[mt][nt][0] + b0, acc[mt][nt][1] + b1);
            *(float2*)(C + (size_t)(row + 8) * N + col) =
                make_float2(acc[mt][nt][2] + b0, acc[mt][nt][3] + b1);
        }
    }
}

// ===========================================================================
// Flash attention on mma.sync tf32 (unchanged from passing round-4 version).
// ===========================================================================
__global__ __launch_bounds__(256) void mma_attn(
    const float* __restrict__ qkv, float* __restrict__ outp)
{
    __shared__ uint32_t Ksm[4096];  // 8 s-tile x 8 kf(d) x 32 lane x 2
    __shared__ uint32_t Vsm[4096];  // 8 d-tile x 8 kf(s) x 32 lane x 2

    const int tid  = threadIdx.x;
    const int lane = tid & 31, wq = tid >> 5;
    const int g = lane >> 2, t4 = lane & 3;
    const int b = blockIdx.z, h = blockIdx.y, q0 = blockIdx.x * 128;

    uint32_t qa[8][4];
    {
        const float scale = 0.125f;  // 1/sqrt(64)
        const size_t r0 = (size_t)(b * SEQ + q0 + wq * 16 + g) * E3 + h * HD;
        const size_t r1 = r0 + (size_t)8 * E3;
        #pragma unroll
        for (int kf = 0; kf < 8; kf++) {
            const int c = kf * 8 + t4;
            qa[kf][0] = tf32_of(qkv[r0 + c] * scale);
            qa[kf][1] = tf32_of(qkv[r1 + c] * scale);
            qa[kf][2] = tf32_of(qkv[r0 + c + 4] * scale);
            qa[kf][3] = tf32_of(qkv[r1 + c + 4] * scale);
        }
    }

    float O[8][4];
    #pragma unroll
    for (int nt = 0; nt < 8; nt++)
        #pragma unroll
        for (int j = 0; j < 4; j++) O[nt][j] = 0.f;
    float m0 = -INFINITY, m1 = -INFINITY, l0 = 0.f, l1 = 0.f;

    const int sR = tid >> 2, dB = (tid & 3) * 16;
    float4 kR[4], vR[4];
    {
        const size_t base = (size_t)(b * SEQ + sR) * E3 + h * HD + dB;
        #pragma unroll
        for (int i = 0; i < 4; i++) {
            kR[i] = *(const float4*)(qkv + base + EMB + i * 4);
            vR[i] = *(const float4*)(qkv + base + 2 * EMB + i * 4);
        }
    }

    for (int kb = 0; kb < SEQ; kb += 64) {
        #pragma unroll
        for (int i = 0; i < 4; i++) {
            float kv[4] = {kR[i].x, kR[i].y, kR[i].z, kR[i].w};
            float vv[4] = {vR[i].x, vR[i].y, vR[i].z, vR[i].w};
            #pragma unroll
            for (int j = 0; j < 4; j++) {
                const int d = dB + i * 4 + j;
                const int kidx = ((((sR >> 3) * 8 + (d >> 3)) * 32
                                   + (sR & 7) * 4 + (d & 3)) << 1) + ((d >> 2) & 1);
                Ksm[kidx] = tf32_of(kv[j]);
                const int vidx = ((((d >> 3) * 8 + (sR >> 3)) * 32
                                   + (d & 7) * 4 + (sR & 3)) << 1) + ((sR >> 2) & 1);
                Vsm[vidx] = tf32_of(vv[j]);
            }
        }
        __syncthreads();

        if (kb + 64 < SEQ) {
            const size_t base = (size_t)(b * SEQ + kb + 64 + sR) * E3 + h * HD + dB;
            #pragma unroll
            for (int i = 0; i < 4; i++) {
                kR[i] = *(const float4*)(qkv + base + EMB + i * 4);
                vR[i] = *(const float4*)(qkv + base + 2 * EMB + i * 4);
            }
        }

        float sc[8][4];
        #pragma unroll
        for (int nt = 0; nt < 8; nt++)
            #pragma unroll
            for (int j = 0; j < 4; j++) sc[nt][j] = 0.f;
        #pragma unroll
        for (int kf = 0; kf < 8; kf++) {
            #pragma unroll
            for (int nt = 0; nt < 8; nt++) {
                uint2 v = *(const uint2*)&Ksm[((nt * 8 + kf) * 32 + lane) * 2];
                uint32_t bb[2] = {v.x, v.y};
                mma_tf32(sc[nt], qa[kf], bb);
            }
        }

        float mx0 = -INFINITY, mx1 = -INFINITY;
        #pragma unroll
        for (int nt = 0; nt < 8; nt++) {
            mx0 = fmaxf(mx0, fmaxf(sc[nt][0], sc[nt][1]));
            mx1 = fmaxf(mx1, fmaxf(sc[nt][2], sc[nt][3]));
        }
        mx0 = fmaxf(mx0, __shfl_xor_sync(0xffffffffu, mx0, 1));
        mx0 = fmaxf(mx0, __shfl_xor_sync(0xffffffffu, mx0, 2));
        mx1 = fmaxf(mx1, __shfl_xor_sync(0xffffffffu, mx1, 1));
        mx1 = fmaxf(mx1, __shfl_xor_sync(0xffffffffu, mx1, 2));
        const float mn0 = fmaxf(m0, mx0), mn1 = fmaxf(m1, mx1);
        const float corr0 = __expf(m0 - mn0), corr1 = __expf(m1 - mn1);
        m0 = mn0; m1 = mn1;
        float rs0 = 0.f, rs1 = 0.f;
        #pragma unroll
        for (int nt = 0; nt < 8; nt++) {
            sc[nt][0] = __expf(sc[nt][0] - mn0);
            sc[nt][1] = __expf(sc[nt][1] - mn0);
            sc[nt][2] = __expf(sc[nt][2] - mn1);
            sc[nt][3] = __expf(sc[nt][3] - mn1);
            rs0 += sc[nt][0] + sc[nt][1];
            rs1 += sc[nt][2] + sc[nt][3];
        }
        rs0 += __shfl_xor_sync(0xffffffffu, rs0, 1);
        rs0 += __shfl_xor_sync(0xffffffffu, rs0, 2);
        rs1 += __shfl_xor_sync(0xffffffffu, rs1, 1);
        rs1 += __shfl_xor_sync(0xffffffffu, rs1, 2);
        l0 = l0 * corr0 + rs0;
        l1 = l1 * corr1 + rs1;
        #pragma unroll
        for (int nt = 0; nt < 8; nt++) {
            O[nt][0] *= corr0; O[nt][1] *= corr0;
            O[nt][2] *= corr1; O[nt][3] *= corr1;
        }

        const int qb = lane & ~3;
        const int src0 = qb + (t4 >> 1), src1 = src0 + 2;
        const bool odd = (t4 & 1);
        #pragma unroll
        for (int kf = 0; kf < 8; kf++) {
            float w00 = __shfl_sync(0xffffffffu, sc[kf][0], src0);
            float w01 = __shfl_sync(0xffffffffu, sc[kf][1], src0);
            float w10 = __shfl_sync(0xffffffffu, sc[kf][2], src0);
            float w11 = __shfl_sync(0xffffffffu, sc[kf][3], src0);
            float w20 = __shfl_sync(0xffffffffu, sc[kf][0], src1);
            float w21 = __shfl_sync(0xffffffffu, sc[kf][1], src1);
            float w30 = __shfl_sync(0xffffffffu, sc[kf][2], src1);
            float w31 = __shfl_sync(0xffffffffu, sc[kf][3], src1);
            uint32_t pa[4];
            pa[0] = tf32_of(odd ? w01 : w00);
            pa[1] = tf32_of(odd ? w11 : w10);
            pa[2] = tf32_of(odd ? w21 : w20);
            pa[3] = tf32_of(odd ? w31 : w30);
            #pragma unroll
            for (int nt = 0; nt < 8; nt++) {
                uint2 v = *(const uint2*)&Vsm[((nt * 8 + kf) * 32 + lane) * 2];
                uint32_t bb[2] = {v.x, v.y};
                mma_tf32(O[nt], pa, bb);
            }
        }
        __syncthreads();
    }

    const float inv0 = 1.f / l0, inv1 = 1.f / l1;
    const size_t ro = (size_t)(b * SEQ + q0 + wq * 16 + g) * EMB + h * HD;
    #pragma unroll
    for (int nt = 0; nt < 8; nt++) {
        const int c = nt * 8 + t4 * 2;
        *(float2*)(outp + ro + c) = make_float2(O[nt][0] * inv0, O[nt][1] * inv0);
        *(float2*)(outp + ro + (size_t)8 * EMB + c) =
            make_float2(O[nt][2] * inv1, O[nt][3] * inv1);
    }
}

// ---------------------------------------------------------------------------
extern "C" void kernel_launch(void* const* d_in, const int* in_sizes, int n_in,
                              void* d_out, int out_size)
{
    const float* x     = (const float*)d_in[0];
    const float* w_in  = (const float*)d_in[1];
    const float* b_in  = (const float*)d_in[2];
    const float* w_out = (const float*)d_in[3];
    const float* b_out = (const float*)d_in[4];
    float* out = (float*)d_out;

    float *qkv = nullptr, *attn = nullptr;
    cudaGetSymbolAddress((void**)&qkv,  g_qkv);
    cudaGetSymbolAddress((void**)&attn, g_attn);

    cudaFuncSetAttribute(mma_gemm_bias,
                         cudaFuncAttributeMaxDynamicSharedMemorySize,
                         GEMM_SMEM_BYTES);

    // 1) QKV projection: [4096,1024] @ [1024,3072] + b_in
    mma_gemm_bias<<<dim3(E3 / 128, ROWS / 128), 256, GEMM_SMEM_BYTES>>>(
        x, w_in, b_in, qkv, ROWS, E3, EMB);

    // 2) Fused attention
    mma_attn<<<dim3(SEQ / 128, NH, BATCH), 256>>>(qkv, attn);

    // 3) Output projection: [4096,1024] @ [1024,1024] + b_out
    mma_gemm_bias<<<dim3(EMB / 128, ROWS / 128), 256, GEMM_SMEM_BYTES>>>(
        attn, w_out, b_out, out, ROWS, EMB, EMB);
}

// round 8
// speedup vs baseline: 3.3086x; 1.1285x over previous
#include <cuda_runtime.h>
#include <math.h>
#include <stdint.h>

#define BATCH 2
#define SEQ   2048
#define EMB   1024
#define NH    16
#define HD    64
#define ROWS  (BATCH*SEQ)      /* 4096 */
#define E3    (3*EMB)          /* 3072 */

// Scratch (allocation-free rule: __device__ globals)
__device__ float g_qkv[(size_t)ROWS * E3];    // [4096, 3072]
__device__ float g_attn[(size_t)ROWS * EMB];  // [4096, 1024]
__device__ float g_xr[(size_t)ROWS * EMB];    // x rounded to tf32
__device__ float g_win[(size_t)EMB * E3];     // w_in rounded to tf32
__device__ float g_wout[(size_t)EMB * EMB];   // w_out rounded to tf32

// ===========================================================================
// mma.sync m16n8k8 tf32 helpers
//  A(16x8): a0=(g,t) a1=(g+8,t) a2=(g,t+4) a3=(g+8,t+4)   g=lane>>2, t=lane&3
//  B(8x8) : b0=(k=t, n=g)  b1=(k=t+4, n=g)
//  C(16x8): c0=(g,2t) c1=(g,2t+1) c2=(g+8,2t) c3=(g+8,2t+1)
// ===========================================================================
__device__ __forceinline__ uint32_t tf32_of(float x) {
    uint32_t r;
    asm("cvt.rna.tf32.f32 %0, %1;" : "=r"(r) : "f"(x));
    return r;
}
__device__ __forceinline__ float rndf(float x) {
    return __uint_as_float(tf32_of(x));
}
__device__ __forceinline__ void mma_tf32(float c[4], const uint32_t a[4],
                                         const uint32_t b[2]) {
    asm volatile(
        "mma.sync.aligned.m16n8k8.row.col.f32.tf32.tf32.f32 "
        "{%0,%1,%2,%3}, {%4,%5,%6,%7}, {%8,%9}, {%0,%1,%2,%3};"
        : "+f"(c[0]), "+f"(c[1]), "+f"(c[2]), "+f"(c[3])
        : "r"(a[0]), "r"(a[1]), "r"(a[2]), "r"(a[3]), "r"(b[0]), "r"(b[1]));
}
__device__ __forceinline__ void cp16(uint32_t dst, const void* src) {
    asm volatile("cp.async.cg.shared.global [%0], [%1], 16;"
                 :: "r"(dst), "l"(src));
}
__device__ __forceinline__ uint32_t smem_u32(const void* p) {
    uint32_t a;
    asm("{ .reg .u64 t; cvta.to.shared.u64 t, %1; cvt.u32.u64 %0, t; }"
        : "=r"(a) : "l"(p));
    return a;
}

// ===========================================================================
// Pre-round to tf32 (rna): makes downstream MMA truncation lossless.
// ===========================================================================
__global__ __launch_bounds__(256) void round_tf32_kernel(
    const float* __restrict__ in, float* __restrict__ out, int n4)
{
    for (int i = blockIdx.x * blockDim.x + threadIdx.x; i < n4;
         i += gridDim.x * blockDim.x) {
        float4 v = *(const float4*)(in + (size_t)i * 4);
        v.x = rndf(v.x); v.y = rndf(v.y); v.z = rndf(v.z); v.w = rndf(v.w);
        *(float4*)(out + (size_t)i * 4) = v;
    }
}

// ===========================================================================
// GEMM + bias: C[M,N] = A[M,K] @ B[K,N] + bias[N]
// 128x128 CTA tile, BK=32, 3-stage cp.async, 256 threads (2m x 4n warps).
// RND: round output to tf32 (so the next MMA stage truncates losslessly).
// ===========================================================================
#define GS 3
#define GEMM_SMEM_BYTES (GS * 32768)

template<bool RND>
__global__ __launch_bounds__(256, 2) void mma_gemm_bias(
    const float* __restrict__ A, const float* __restrict__ B,
    const float* __restrict__ bias, float* __restrict__ C,
    int M, int N, int K)
{
    extern __shared__ uint32_t sm[];
    const uint32_t sbase = smem_u32(sm);
    const int tid  = threadIdx.x;
    const int lane = tid & 31, wid = tid >> 5;
    const int wm = wid >> 2, wn = wid & 3;
    const int g = lane >> 2, t4 = lane & 3;
    const int bm = blockIdx.y * 128, bn = blockIdx.x * 128;

    const int ar0 = tid >> 3, ac = tid & 7;
    const int bk0 = tid >> 5, bc = tid & 31;

    float acc[4][4][4];
    #pragma unroll
    for (int mt = 0; mt < 4; mt++)
        #pragma unroll
        for (int nt = 0; nt < 4; nt++)
            #pragma unroll
            for (int j = 0; j < 4; j++) acc[mt][nt][j] = 0.f;

    const int NT = K / 32;

    auto issue = [&](int slot, int kt) {
        const uint32_t aw = sbase + slot * 32768;
        #pragma unroll
        for (int i = 0; i < 4; i++) {
            const int r = ar0 + i * 32;
            cp16(aw + (uint32_t)(r * 32 + ((ac ^ (r & 7)) << 2)) * 4,
                 A + (size_t)(bm + r) * K + kt * 32 + ac * 4);
        }
        const uint32_t bw = aw + 16384;
        #pragma unroll
        for (int i = 0; i < 4; i++) {
            const int k = bk0 + i * 8;
            cp16(bw + (uint32_t)(k * 128 + ((bc ^ (k & 7)) << 2)) * 4,
                 B + (size_t)(kt * 32 + k) * N + bn + bc * 4);
        }
    };

    #pragma unroll
    for (int s = 0; s < GS - 1; s++) {
        issue(s, s);
        asm volatile("cp.async.commit_group;" ::: "memory");
    }

    for (int kt = 0; kt < NT; kt++) {
        asm volatile("cp.async.wait_group 1;" ::: "memory");
        __syncthreads();

        const int slot = kt % GS;
        if (kt + GS - 1 < NT) issue((kt + GS - 1) % GS, kt + GS - 1);
        asm volatile("cp.async.commit_group;" ::: "memory");

        const uint32_t* Aw = sm + slot * 8192;
        const uint32_t* Bw = Aw + 4096;

        #pragma unroll
        for (int kf = 0; kf < 4; kf++) {
            uint32_t af[4][4];
            const int x = (2 * kf) ^ g;
            #pragma unroll
            for (int mt = 0; mt < 4; mt++) {
                const uint32_t* p = Aw + (wm * 64 + mt * 16 + g) * 32 + t4;
                af[mt][0] = p[x << 2];
                af[mt][1] = p[256 + (x << 2)];
                af[mt][2] = p[(x ^ 1) << 2];
                af[mt][3] = p[256 + ((x ^ 1) << 2)];
            }
            uint32_t bf[4][2];
            const uint32_t* q = Bw + (kf * 8 + t4) * 128 + (g & 3);
            #pragma unroll
            for (int nt = 0; nt < 4; nt++) {
                const int ct = (wn * 8 + nt * 2 + (g >> 2)) ^ t4;
                bf[nt][0] = q[ct << 2];
                bf[nt][1] = q[512 + ((ct ^ 4) << 2)];
            }
            #pragma unroll
            for (int mt = 0; mt < 4; mt++)
                #pragma unroll
                for (int nt = 0; nt < 4; nt++)
                    mma_tf32(acc[mt][nt], af[mt], bf[nt]);
        }
    }

    #pragma unroll
    for (int mt = 0; mt < 4; mt++) {
        const int row = bm + wm * 64 + mt * 16 + g;
        #pragma unroll
        for (int nt = 0; nt < 4; nt++) {
            const int col = bn + wn * 32 + nt * 8 + t4 * 2;
            const float b0 = bias[col], b1 = bias[col + 1];
            float2 v0 = make_float2(acc[mt][nt][0] + b0, acc[mt][nt][1] + b1);
            float2 v1 = make_float2(acc[mt][nt][2] + b0, acc[mt][nt][3] + b1);
            if (RND) {
                v0.x = rndf(v0.x); v0.y = rndf(v0.y);
                v1.x = rndf(v1.x); v1.y = rndf(v1.y);
            }
            *(float2*)(C + (size_t)row * N + col) = v0;
            *(float2*)(C + (size_t)(row + 8) * N + col) = v1;
        }
    }
}

// ===========================================================================
// Flash attention, mma.sync tf32, cp.async double-buffered K/V staging.
// CTA = (128 q, head, batch); 8 warps x 16 q-rows. BN=64 keys/iter.
// K tile smem [s=64][d=64] fp32, chunk swizzle c ^= s&7 (c = d>>2).
// V tile smem [s=64][d=64] fp32, same swizzle. 2 bufs x 32KB = 64KB.
// Fragment loads: scalar LDS, conflict-free (K) / <=2-way (V).
// Output rounded to tf32 so out-proj truncation is lossless.
// ===========================================================================
#define ATTN_SMEM_BYTES 65536

__global__ __launch_bounds__(256, 2) void mma_attn(
    const float* __restrict__ qkv, float* __restrict__ outp)
{
    extern __shared__ uint32_t smA[];
    const uint32_t sbase = smem_u32(smA);

    const int tid  = threadIdx.x;
    const int lane = tid & 31, wq = tid >> 5;
    const int g = lane >> 2, t4 = lane & 3;
    const int b = blockIdx.z, h = blockIdx.y, q0 = blockIdx.x * 128;

    // ---- Q fragments (pre-scaled; qkv already tf32 so rna is exact) ----
    uint32_t qa[8][4];
    {
        const float scale = 0.125f;  // 1/sqrt(64), power of 2: stays tf32-exact
        const size_t r0 = (size_t)(b * SEQ + q0 + wq * 16 + g) * E3 + h * HD;
        const size_t r1 = r0 + (size_t)8 * E3;
        #pragma unroll
        for (int kf = 0; kf < 8; kf++) {
            const int c = kf * 8 + t4;
            qa[kf][0] = tf32_of(qkv[r0 + c] * scale);
            qa[kf][1] = tf32_of(qkv[r1 + c] * scale);
            qa[kf][2] = tf32_of(qkv[r0 + c + 4] * scale);
            qa[kf][3] = tf32_of(qkv[r1 + c + 4] * scale);
        }
    }

    float O[8][4];
    #pragma unroll
    for (int nt = 0; nt < 8; nt++)
        #pragma unroll
        for (int j = 0; j < 4; j++) O[nt][j] = 0.f;
    float m0 = -INFINITY, m1 = -INFINITY, l0 = 0.f, l1 = 0.f;

    // cp.async staging role: thread -> (s row, 4 chunks of 4 floats)
    const int sR = tid >> 2, c0 = (tid & 3) * 4;
    auto issue = [&](int buf, int kb) {
        const size_t gbase = (size_t)(b * SEQ + kb + sR) * E3 + h * HD;
        const uint32_t krow = sbase + buf * 32768 + sR * 256;
        #pragma unroll
        for (int i = 0; i < 4; i++) {
            const int c = c0 + i;
            const uint32_t csw = (uint32_t)(c ^ (sR & 7)) << 4;
            cp16(krow + csw,         qkv + gbase + EMB + c * 4);
            cp16(krow + 16384 + csw, qkv + gbase + 2 * EMB + c * 4);
        }
    };

    issue(0, 0);
    asm volatile("cp.async.commit_group;" ::: "memory");

    const int NB = SEQ / 64;
    for (int it = 0; it < NB; it++) {
        asm volatile("cp.async.wait_group 0;" ::: "memory");
        __syncthreads();
        if (it + 1 < NB) {
            issue((it + 1) & 1, (it + 1) * 64);
            asm volatile("cp.async.commit_group;" ::: "memory");
        }

        const uint32_t* Kw = smA + (it & 1) * 8192;
        const uint32_t* Vw = Kw + 4096;

        // ---- S = Q @ K^T : B-frag (n=s, k=d) from K[s][d] ----
        float sc[8][4];
        #pragma unroll
        for (int nt = 0; nt < 8; nt++)
            #pragma unroll
            for (int j = 0; j < 4; j++) sc[nt][j] = 0.f;
        #pragma unroll
        for (int kf = 0; kf < 8; kf++) {
            const int x0 = (2 * kf) ^ g;
            #pragma unroll
            for (int nt = 0; nt < 8; nt++) {
                const uint32_t* p = Kw + (nt * 8 + g) * 64 + t4;
                uint32_t bb[2] = {p[x0 << 2], p[(x0 ^ 1) << 2]};
                mma_tf32(sc[nt], qa[kf], bb);
            }
        }

        // ---- online softmax (rows g, g+8; quad-local reductions) ----
        float mx0 = -INFINITY, mx1 = -INFINITY;
        #pragma unroll
        for (int nt = 0; nt < 8; nt++) {
            mx0 = fmaxf(mx0, fmaxf(sc[nt][0], sc[nt][1]));
            mx1 = fmaxf(mx1, fmaxf(sc[nt][2], sc[nt][3]));
        }
        mx0 = fmaxf(mx0, __shfl_xor_sync(0xffffffffu, mx0, 1));
        mx0 = fmaxf(mx0, __shfl_xor_sync(0xffffffffu, mx0, 2));
        mx1 = fmaxf(mx1, __shfl_xor_sync(0xffffffffu, mx1, 1));
        mx1 = fmaxf(mx1, __shfl_xor_sync(0xffffffffu, mx1, 2));
        const float mn0 = fmaxf(m0, mx0), mn1 = fmaxf(m1, mx1);
        const float corr0 = __expf(m0 - mn0), corr1 = __expf(m1 - mn1);
        m0 = mn0; m1 = mn1;
        float rs0 = 0.f, rs1 = 0.f;
        #pragma unroll
        for (int nt = 0; nt < 8; nt++) {
            sc[nt][0] = __expf(sc[nt][0] - mn0);
            sc[nt][1] = __expf(sc[nt][1] - mn0);
            sc[nt][2] = __expf(sc[nt][2] - mn1);
            sc[nt][3] = __expf(sc[nt][3] - mn1);
            rs0 += sc[nt][0] + sc[nt][1];
            rs1 += sc[nt][2] + sc[nt][3];
        }
        rs0 += __shfl_xor_sync(0xffffffffu, rs0, 1);
        rs0 += __shfl_xor_sync(0xffffffffu, rs0, 2);
        rs1 += __shfl_xor_sync(0xffffffffu, rs1, 1);
        rs1 += __shfl_xor_sync(0xffffffffu, rs1, 2);
        l0 = l0 * corr0 + rs0;
        l1 = l1 * corr1 + rs1;
        #pragma unroll
        for (int nt = 0; nt < 8; nt++) {
            O[nt][0] *= corr0; O[nt][1] *= corr0;
            O[nt][2] *= corr1; O[nt][3] *= corr1;
        }

        // ---- O += P @ V : P C-frag -> A-frag via quad shuffles ----
        const int qb = lane & ~3;
        const int src0 = qb + (t4 >> 1), src1 = src0 + 2;
        const bool odd = (t4 & 1);
        #pragma unroll
        for (int kf = 0; kf < 8; kf++) {
            float w00 = __shfl_sync(0xffffffffu, sc[kf][0], src0);
            float w01 = __shfl_sync(0xffffffffu, sc[kf][1], src0);
            float w10 = __shfl_sync(0xffffffffu, sc[kf][2], src0);
            float w11 = __shfl_sync(0xffffffffu, sc[kf][3], src0);
            float w20 = __shfl_sync(0xffffffffu, sc[kf][0], src1);
            float w21 = __shfl_sync(0xffffffffu, sc[kf][1], src1);
            float w30 = __shfl_sync(0xffffffffu, sc[kf][2], src1);
            float w31 = __shfl_sync(0xffffffffu, sc[kf][3], src1);
            uint32_t pa[4];
            pa[0] = tf32_of(odd ? w01 : w00);
            pa[1] = tf32_of(odd ? w11 : w10);
            pa[2] = tf32_of(odd ? w21 : w20);
            pa[3] = tf32_of(odd ? w31 : w30);
            // B-frag (n=d, k=s) from V[s][d]
            #pragma unroll
            for (int nt = 0; nt < 8; nt++) {
                const int cv = nt * 2 + (g >> 2);
                const uint32_t b0 =
                    Vw[(kf * 8 + t4) * 64 + ((cv ^ t4) << 2) + (g & 3)];
                const uint32_t b1 =
                    Vw[(kf * 8 + t4 + 4) * 64 + ((cv ^ t4 ^ 4) << 2) + (g & 3)];
                uint32_t bb[2] = {b0, b1};
                mma_tf32(O[nt], pa, bb);
            }
        }
    }

    // ---- normalize + round to tf32 + store ----
    const float inv0 = 1.f / l0, inv1 = 1.f / l1;
    const size_t ro = (size_t)(b * SEQ + q0 + wq * 16 + g) * EMB + h * HD;
    #pragma unroll
    for (int nt = 0; nt < 8; nt++) {
        const int c = nt * 8 + t4 * 2;
        *(float2*)(outp + ro + c) =
            make_float2(rndf(O[nt][0] * inv0), rndf(O[nt][1] * inv0));
        *(float2*)(outp + ro + (size_t)8 * EMB + c) =
            make_float2(rndf(O[nt][2] * inv1), rndf(O[nt][3] * inv1));
    }
}

// ---------------------------------------------------------------------------
extern "C" void kernel_launch(void* const* d_in, const int* in_sizes, int n_in,
                              void* d_out, int out_size)
{
    const float* x     = (const float*)d_in[0];
    const float* w_in  = (const float*)d_in[1];
    const float* b_in  = (const float*)d_in[2];
    const float* w_out = (const float*)d_in[3];
    const float* b_out = (const float*)d_in[4];
    float* out = (float*)d_out;

    float *qkv, *attn, *xr, *win, *wout;
    cudaGetSymbolAddress((void**)&qkv,  g_qkv);
    cudaGetSymbolAddress((void**)&attn, g_attn);
    cudaGetSymbolAddress((void**)&xr,   g_xr);
    cudaGetSymbolAddress((void**)&win,  g_win);
    cudaGetSymbolAddress((void**)&wout, g_wout);

    cudaFuncSetAttribute(mma_gemm_bias<true>,
                         cudaFuncAttributeMaxDynamicSharedMemorySize,
                         GEMM_SMEM_BYTES);
    cudaFuncSetAttribute(mma_gemm_bias<false>,
                         cudaFuncAttributeMaxDynamicSharedMemorySize,
                         GEMM_SMEM_BYTES);
    cudaFuncSetAttribute(mma_attn,
                         cudaFuncAttributeMaxDynamicSharedMemorySize,
                         ATTN_SMEM_BYTES);

    // 0) Pre-round inputs/weights to tf32 (rna) so MMA truncation is exact
    round_tf32_kernel<<<592, 256>>>(x,     xr,   ROWS * EMB / 4);
    round_tf32_kernel<<<592, 256>>>(w_in,  win,  EMB * E3 / 4);
    round_tf32_kernel<<<592, 256>>>(w_out, wout, EMB * EMB / 4);

    // 1) QKV projection (output rounded to tf32)
    mma_gemm_bias<true><<<dim3(E3 / 128, ROWS / 128), 256, GEMM_SMEM_BYTES>>>(
        xr, win, b_in, qkv, ROWS, E3, EMB);

    // 2) Fused attention (output rounded to tf32)
    mma_attn<<<dim3(SEQ / 128, NH, BATCH), 256, ATTN_SMEM_BYTES>>>(qkv, attn);

    // 3) Output projection (full fp32 output)
    mma_gemm_bias<false><<<dim3(EMB / 128, ROWS / 128), 256, GEMM_SMEM_BYTES>>>(
        attn, wout, b_out, out, ROWS, EMB, EMB);
}